// round 1
// baseline (speedup 1.0000x reference)
#include <cuda_runtime.h>
#include <cstddef>

// ---- problem constants ----
#define HH 384
#define WW 384
#define NPIX (HH*WW)          // 147456
#define BB 4
#define MM 192
#define NTHREADS 512
#define PPT 8
#define PIX_PER_BLOCK (NTHREADS*PPT)   // 4096
#define NCHUNK (NPIX/PIX_PER_BLOCK)    // 36  -> grid = 36 x 4 = 144 blocks (1 wave)
#define NWARP (NTHREADS/32)            // 16
#define EPSF 1e-6f
#define MAX_DISTF 543.0580079975699f   // sqrt(384^2+384^2)
#define EPS_OVER_MAX 1.8414263e-9f     // 1e-6 / MAX_DIST (double-precision derived)
#define BIGF 3.4e38f

// ---- scratch (no device allocation allowed; static globals) ----
__device__ float g_t1part[BB*NCHUNK];
__device__ float g_ppart [BB*NCHUNK];
__device__ float g_jmin  [BB*NCHUNK*MM];

__global__ __launch_bounds__(NTHREADS)
void whd_main(const float* __restrict__ pm,
              const float* __restrict__ gt,
              const float* __restrict__ osz)
{
    __shared__ float2 s_gt[MM];
    __shared__ float  s_wk[MM*(NWARP+1)];   // per-warp key minima, stride 17 (bank-conflict free)
    __shared__ float  s_wc[MM*(NWARP+1)];   // per-warp csq at argmin
    __shared__ float  s_red[NWARP*2];

    const int tid  = threadIdx.x;
    const int lane = tid & 31;
    const int wid  = tid >> 5;
    const int chunk = blockIdx.x;
    const int b     = blockIdx.y;

    const float fy = osz[2*b+0] * (1.0f/(float)HH);
    const float fx = osz[2*b+1] * (1.0f/(float)WW);

    if (tid < MM) {
        float gy = gt[((size_t)b*MM + tid)*2 + 0] * fy;
        float gx = gt[((size_t)b*MM + tid)*2 + 1] * fx;
        s_gt[tid] = make_float2(gx, gy);
    }

    // -------- stage per-pixel state into registers --------
    float nx[PPT], ny[PPT], csq[PPT], pv[PPT], d2min[PPT];
    const float* pmb = pm + (size_t)b * NPIX;
    const int base = chunk * PIX_PER_BLOCK;
#pragma unroll
    for (int k = 0; k < PPT; ++k) {
        int pix = base + k*NTHREADS + tid;        // coalesced
        float p = pmb[pix];
        int y = pix / WW;
        int x = pix - y*WW;
        nx[k] = (float)x * fx;
        ny[k] = (float)y * fy;
        float pp = p*p;
        float denom = pp*pp + EPS_OVER_MAX;       // p^4 + eps/MAX_DIST
        float c = 1.0f / denom;
        csq[k]   = c*c;
        pv[k]    = p;
        d2min[k] = BIGF;
    }
    __syncthreads();

    // -------- main pair loop: all 192 GT points x this thread's 8 pixels --------
#pragma unroll 2
    for (int j = 0; j < MM; ++j) {
        float2 g = s_gt[j];                       // LDS.64 broadcast
        float kmin = BIGF, cmin = 0.f;
#pragma unroll
        for (int k = 0; k < PPT; ++k) {
            float dx = nx[k] - g.x;
            float dy = ny[k] - g.y;
            float d2 = fmaf(dx, dx, dy*dy);
            d2min[k] = fminf(d2min[k], d2);       // term1: min over j per pixel
            float key = d2 * csq[k];              // (d*c)^2 ordering key for term2
            if (key < kmin) { kmin = key; cmin = csq[k]; }
        }
        // warp-reduce (kmin, cmin) pair
#pragma unroll
        for (int off = 16; off > 0; off >>= 1) {
            float ok = __shfl_down_sync(0xffffffffu, kmin, off);
            float oc = __shfl_down_sync(0xffffffffu, cmin, off);
            if (ok < kmin) { kmin = ok; cmin = oc; }
        }
        if (lane == 0) {
            s_wk[j*(NWARP+1)+wid] = kmin;
            s_wc[j*(NWARP+1)+wid] = cmin;
        }
    }

    // -------- term1 partial: sum p * sqrt(min d2), and sum p --------
    float t1 = 0.f, ps = 0.f;
#pragma unroll
    for (int k = 0; k < PPT; ++k) { t1 += pv[k]*sqrtf(d2min[k]); ps += pv[k]; }
#pragma unroll
    for (int off = 16; off > 0; off >>= 1) {
        t1 += __shfl_down_sync(0xffffffffu, t1, off);
        ps += __shfl_down_sync(0xffffffffu, ps, off);
    }
    if (lane == 0) { s_red[wid] = t1; s_red[NWARP+wid] = ps; }
    __syncthreads();
    if (tid == 0) {
        float a = 0.f, c2 = 0.f;
        for (int w = 0; w < NWARP; ++w) { a += s_red[w]; c2 += s_red[NWARP+w]; }
        g_t1part[b*NCHUNK + chunk] = a;
        g_ppart [b*NCHUNK + chunk] = c2;
    }

    // -------- term2: combine per-warp minima into per-block per-j value --------
    if (tid < MM) {
        int j = tid;
        float kmin = BIGF, cmin = 0.f;
#pragma unroll
        for (int w = 0; w < NWARP; ++w) {
            float k2 = s_wk[j*(NWARP+1)+w];
            float c2 = s_wc[j*(NWARP+1)+w];
            if (k2 < kmin) { kmin = k2; cmin = c2; }
        }
        // exact objective at selected pixel: sqrt(d2)*c + eps*c
        float v = sqrtf(kmin) + EPSF * sqrtf(cmin);
        g_jmin[((size_t)b*NCHUNK + chunk)*MM + j] = v;
    }
}

__global__ void whd_final(float* __restrict__ out)
{
    __shared__ float s_t2[256];
    __shared__ float s_t1[BB];
    int tid = threadIdx.x;

    if (tid < BB) {
        float num = 0.f, den = 0.f;
        for (int c = 0; c < NCHUNK; ++c) {
            num += g_t1part[tid*NCHUNK + c];
            den += g_ppart [tid*NCHUNK + c];
        }
        s_t1[tid] = num / (den + EPSF);
    }

    float acc = 0.f;
    for (int t = tid; t < BB*MM; t += 256) {
        int b = t / MM, j = t - b*MM;
        float v = BIGF;
        for (int c = 0; c < NCHUNK; ++c)
            v = fminf(v, g_jmin[((size_t)b*NCHUNK + c)*MM + j]);
        v = fminf(v, MAX_DISTF);   // clip(., 0, MAX_DIST); v >= 0 always
        acc += v;
    }
    s_t2[tid] = acc;
    __syncthreads();

    if (tid == 0) {
        float s = 0.f;
        for (int i = 0; i < 256; ++i) s += s_t2[i];
        float t1 = 0.f;
        for (int b = 0; b < BB; ++b) t1 += s_t1[b];
        out[0] = t1 * (1.0f/(float)BB) + s * (1.0f/(float)(BB*MM));
    }
}

extern "C" void kernel_launch(void* const* d_in, const int* in_sizes, int n_in,
                              void* d_out, int out_size)
{
    // identify inputs by element count (robust to metadata ordering)
    const float* pm  = nullptr;
    const float* gt  = nullptr;
    const float* osz = nullptr;
    for (int i = 0; i < n_in; ++i) {
        if      (in_sizes[i] == BB*NPIX) pm  = (const float*)d_in[i];
        else if (in_sizes[i] == BB*MM*2) gt  = (const float*)d_in[i];
        else if (in_sizes[i] == BB*2)    osz = (const float*)d_in[i];
    }
    dim3 grid(NCHUNK, BB);
    whd_main<<<grid, NTHREADS>>>(pm, gt, osz);
    whd_final<<<1, 256>>>((float*)d_out);
    (void)out_size;
}

// round 2
// speedup vs baseline: 1.1046x; 1.1046x over previous
#include <cuda_runtime.h>
#include <cstddef>

// ---- problem constants ----
#define HH 384
#define WW 384
#define NPIX (HH*WW)          // 147456
#define BB 4
#define MM 192
#define NTHREADS 256
#define PPT 16
#define PPK (PPT/2)                    // packed f32x2 pairs per thread
#define PIX_PER_BLOCK (NTHREADS*PPT)   // 4096
#define NCHUNK (NPIX/PIX_PER_BLOCK)    // 36  -> grid = 36 x 4 = 144 blocks (1 wave)
#define NWARP (NTHREADS/32)            // 8
#define EPSF 1e-6f
#define MAX_DISTF 543.0580079975699f   // sqrt(384^2+384^2)
#define EPS_OVER_MAX 1.8414263e-9f     // 1e-6 / MAX_DIST
#define BIGF 3.4e38f

// ---- scratch (no device allocation allowed; static globals) ----
__device__ float g_t1part[BB*NCHUNK];
__device__ float g_ppart [BB*NCHUNK];
__device__ float g_jmin  [BB*NCHUNK*MM];

// ---- packed f32x2 helpers (Blackwell FFMA2 path; ptxas won't emit from C++) ----
__device__ __forceinline__ unsigned long long pk2(float a, float b) {
    unsigned long long r;
    asm("mov.b64 %0, {%1, %2};" : "=l"(r) : "f"(a), "f"(b));
    return r;
}
__device__ __forceinline__ void upk2(float& a, float& b, unsigned long long v) {
    asm("mov.b64 {%0, %1}, %2;" : "=f"(a), "=f"(b) : "l"(v));
}
__device__ __forceinline__ unsigned long long addx2(unsigned long long a, unsigned long long b) {
    unsigned long long r;
    asm("add.rn.f32x2 %0, %1, %2;" : "=l"(r) : "l"(a), "l"(b));
    return r;
}
__device__ __forceinline__ unsigned long long mulx2(unsigned long long a, unsigned long long b) {
    unsigned long long r;
    asm("mul.rn.f32x2 %0, %1, %2;" : "=l"(r) : "l"(a), "l"(b));
    return r;
}
__device__ __forceinline__ unsigned long long fmax2(unsigned long long a, unsigned long long b,
                                                    unsigned long long c) {
    unsigned long long r;
    asm("fma.rn.f32x2 %0, %1, %2, %3;" : "=l"(r) : "l"(a), "l"(b), "l"(c));
    return r;
}

__global__ __launch_bounds__(NTHREADS)
void whd_main(const float* __restrict__ pm,
              const float* __restrict__ gt,
              const float* __restrict__ osz)
{
    __shared__ float2 s_gt[MM];                 // NEGATED normalized GT coords (-gx,-gy)
    __shared__ float  s_wk[MM*(NWARP+1)];       // per-warp key minima, stride 9
    __shared__ float  s_wc[MM*(NWARP+1)];       // per-warp csq at argmin
    __shared__ float  s_red[NWARP*2];

    const int tid  = threadIdx.x;
    const int lane = tid & 31;
    const int wid  = tid >> 5;
    const int chunk = blockIdx.x;
    const int b     = blockIdx.y;

    const float fy = osz[2*b+0] * (1.0f/(float)HH);
    const float fx = osz[2*b+1] * (1.0f/(float)WW);

    if (tid < MM) {
        float gy = gt[((size_t)b*MM + tid)*2 + 0] * fy;
        float gx = gt[((size_t)b*MM + tid)*2 + 1] * fx;
        s_gt[tid] = make_float2(-gx, -gy);      // negated so inner loop uses add.f32x2
    }

    // -------- stage per-pixel state into registers (packed pairs) --------
    unsigned long long nxp[PPK], nyp[PPK], csp[PPK];
    float csq[PPT], d2min[PPT];
    const float* pmb = pm + (size_t)b * NPIX;
    const int base = chunk * PIX_PER_BLOCK;
#pragma unroll
    for (int k = 0; k < PPT; ++k) {
        int pix = base + k*NTHREADS + tid;        // coalesced
        float p = pmb[pix];
        int y = pix / WW;
        int x = pix - y*WW;
        float nxs = (float)x * fx;
        float nys = (float)y * fy;
        float pp = p*p;
        float denom = pp*pp + EPS_OVER_MAX;       // p^4 + eps/MAX_DIST
        float c = 1.0f / denom;
        csq[k]   = c*c;
        d2min[k] = BIGF;
        if (k & 1) {
            // pack with previous element
            int kk = k >> 1;
            int pixp = base + (k-1)*NTHREADS + tid;
            int yp = pixp / WW;
            int xp = pixp - yp*WW;
            nxp[kk] = pk2((float)xp * fx, nxs);
            nyp[kk] = pk2((float)yp * fy, nys);
            csp[kk] = pk2(csq[k-1], csq[k]);
        }
    }
    __syncthreads();

    // -------- main pair loop: 192 GT points x 16 pixels/thread --------
    for (int j = 0; j < MM; ++j) {
        float2 g = s_gt[j];                       // LDS.64 broadcast (already negated)
        unsigned long long gx2 = pk2(g.x, g.x);
        unsigned long long gy2 = pk2(g.y, g.y);
        float kmin = BIGF, cmin = 0.f;
#pragma unroll
        for (int kk = 0; kk < PPK; ++kk) {
            unsigned long long dx = addx2(nxp[kk], gx2);
            unsigned long long dy = addx2(nyp[kk], gy2);
            unsigned long long d2 = fmax2(dx, dx, mulx2(dy, dy));
            float d2a, d2b; upk2(d2a, d2b, d2);
            d2min[2*kk]   = fminf(d2min[2*kk],   d2a);   // term1 per-pixel min over j
            d2min[2*kk+1] = fminf(d2min[2*kk+1], d2b);
            unsigned long long key = mulx2(d2, csp[kk]); // (d*c)^2 ordering key
            float ka, kb; upk2(ka, kb, key);
            if (ka < kmin) { kmin = ka; cmin = csq[2*kk];   }
            if (kb < kmin) { kmin = kb; cmin = csq[2*kk+1]; }
        }
        // warp-reduce: redux.min on uint bits (nonneg float -> order preserved)
        unsigned kb_ = __float_as_uint(kmin);
        unsigned rmin = __reduce_min_sync(0xffffffffu, kb_);
        unsigned winners = __ballot_sync(0xffffffffu, kb_ == rmin);
        int src = __ffs(winners) - 1;
        float cw = __shfl_sync(0xffffffffu, cmin, src);
        if (lane == 0) {
            s_wk[j*(NWARP+1)+wid] = __uint_as_float(rmin);
            s_wc[j*(NWARP+1)+wid] = cw;
        }
    }

    // -------- term1 partial: sum p * sqrt(min d2), and sum p (reload p: L2-hot) --------
    float t1 = 0.f, ps = 0.f;
#pragma unroll
    for (int k = 0; k < PPT; ++k) {
        float p = pmb[base + k*NTHREADS + tid];
        t1 += p * sqrtf(d2min[k]);
        ps += p;
    }
#pragma unroll
    for (int off = 16; off > 0; off >>= 1) {
        t1 += __shfl_down_sync(0xffffffffu, t1, off);
        ps += __shfl_down_sync(0xffffffffu, ps, off);
    }
    if (lane == 0) { s_red[wid] = t1; s_red[NWARP+wid] = ps; }
    __syncthreads();
    if (tid == 0) {
        float a = 0.f, c2 = 0.f;
#pragma unroll
        for (int w = 0; w < NWARP; ++w) { a += s_red[w]; c2 += s_red[NWARP+w]; }
        g_t1part[b*NCHUNK + chunk] = a;
        g_ppart [b*NCHUNK + chunk] = c2;
    }

    // -------- term2: combine per-warp minima into per-block per-j value --------
    if (tid < MM) {
        int j = tid;
        float kmin = BIGF, cmin = 0.f;
#pragma unroll
        for (int w = 0; w < NWARP; ++w) {
            float k2 = s_wk[j*(NWARP+1)+w];
            float c2 = s_wc[j*(NWARP+1)+w];
            if (k2 < kmin) { kmin = k2; cmin = c2; }
        }
        // exact objective at selected pixel: sqrt(d2)*c + eps*c
        float v = sqrtf(kmin) + EPSF * sqrtf(cmin);
        g_jmin[((size_t)b*NCHUNK + chunk)*MM + j] = v;
    }
}

__global__ __launch_bounds__(1024)
void whd_final(float* __restrict__ out)
{
    __shared__ float s_wsum[32];
    __shared__ float s_t1[BB];
    __shared__ float s_np[2*BB*NCHUNK];
    const int tid  = threadIdx.x;
    const int lane = tid & 31;
    const int wid  = tid >> 5;

    // stage term1 partials into smem with full parallelism
    if (tid < BB*NCHUNK) {
        s_np[tid]            = g_t1part[tid];
        s_np[BB*NCHUNK+tid]  = g_ppart[tid];
    }

    // term2: one thread per (b,j); unrolled chunk loop -> high MLP
    float acc = 0.f;
    if (tid < BB*MM) {
        int b = tid / MM, j = tid - b*MM;
        const float* p0 = &g_jmin[((size_t)b*NCHUNK)*MM + j];
        float m0 = BIGF, m1 = BIGF, m2 = BIGF, m3 = BIGF;
#pragma unroll
        for (int c = 0; c < NCHUNK; c += 4) {
            m0 = fminf(m0, p0[(size_t)(c+0)*MM]);
            m1 = fminf(m1, p0[(size_t)(c+1)*MM]);
            m2 = fminf(m2, p0[(size_t)(c+2)*MM]);
            m3 = fminf(m3, p0[(size_t)(c+3)*MM]);
        }
        acc = fminf(fminf(fminf(m0, m1), fminf(m2, m3)), MAX_DISTF);
    }
#pragma unroll
    for (int off = 16; off > 0; off >>= 1)
        acc += __shfl_down_sync(0xffffffffu, acc, off);
    if (lane == 0) s_wsum[wid] = acc;
    __syncthreads();

    // term1 ratios (reads from smem, cheap)
    if (tid < BB) {
        float num = 0.f, den = 0.f;
#pragma unroll
        for (int c = 0; c < NCHUNK; ++c) {
            num += s_np[tid*NCHUNK + c];
            den += s_np[BB*NCHUNK + tid*NCHUNK + c];
        }
        s_t1[tid] = num / (den + EPSF);
    }
    __syncthreads();

    if (tid == 0) {
        float s = 0.f;
#pragma unroll
        for (int w = 0; w < 32; ++w) s += s_wsum[w];
        float t1 = 0.f;
#pragma unroll
        for (int b2 = 0; b2 < BB; ++b2) t1 += s_t1[b2];
        out[0] = t1 * (1.0f/(float)BB) + s * (1.0f/(float)(BB*MM));
    }
}

extern "C" void kernel_launch(void* const* d_in, const int* in_sizes, int n_in,
                              void* d_out, int out_size)
{
    const float* pm  = nullptr;
    const float* gt  = nullptr;
    const float* osz = nullptr;
    for (int i = 0; i < n_in; ++i) {
        if      (in_sizes[i] == BB*NPIX) pm  = (const float*)d_in[i];
        else if (in_sizes[i] == BB*MM*2) gt  = (const float*)d_in[i];
        else if (in_sizes[i] == BB*2)    osz = (const float*)d_in[i];
    }
    dim3 grid(NCHUNK, BB);
    whd_main<<<grid, NTHREADS>>>(pm, gt, osz);
    whd_final<<<1, 1024>>>((float*)d_out);
    (void)out_size;
}

// round 3
// speedup vs baseline: 1.9533x; 1.7684x over previous
#include <cuda_runtime.h>
#include <cstddef>

// ---- problem constants ----
#define HH 384
#define WW 384
#define NPIX (HH*WW)          // 147456
#define BB 4
#define MM 192
#define NTHREADS 512
#define PPT 8
#define PPK (PPT/2)                    // packed f32x2 pairs per thread
#define PIX_PER_BLOCK (NTHREADS*PPT)   // 4096
#define NCHUNK (NPIX/PIX_PER_BLOCK)    // 36
#define NBLOCKS (BB*NCHUNK)            // 144  -> exactly 1 wave on 148 SMs
#define NWARP (NTHREADS/32)            // 16
#define EPSF 1e-6f
#define MAX_DISTF 543.0580079975699f   // sqrt(384^2+384^2)
#define EPS_OVER_MAX 1.8414263e-9f     // 1e-6 / MAX_DIST
#define BIGF 3.4e38f

// ---- scratch (static device globals; zero-initialized at module load,
//      and reset back to the same state by the last block each launch) ----
__device__ float    g_t1part[NBLOCKS];
__device__ float    g_ppart [NBLOCKS];
__device__ unsigned g_jmin2 [BB*MM];   // holds ~bits(key); atomicMax; 0 == identity
__device__ unsigned g_sem;             // block-completion counter

// ---- packed f32x2 helpers ----
__device__ __forceinline__ unsigned long long pk2(float a, float b) {
    unsigned long long r;
    asm("mov.b64 %0, {%1, %2};" : "=l"(r) : "f"(a), "f"(b));
    return r;
}
__device__ __forceinline__ void upk2(float& a, float& b, unsigned long long v) {
    asm("mov.b64 {%0, %1}, %2;" : "=f"(a), "=f"(b) : "l"(v));
}
__device__ __forceinline__ unsigned long long addx2(unsigned long long a, unsigned long long b) {
    unsigned long long r;
    asm("add.rn.f32x2 %0, %1, %2;" : "=l"(r) : "l"(a), "l"(b));
    return r;
}
__device__ __forceinline__ unsigned long long mulx2(unsigned long long a, unsigned long long b) {
    unsigned long long r;
    asm("mul.rn.f32x2 %0, %1, %2;" : "=l"(r) : "l"(a), "l"(b));
    return r;
}
__device__ __forceinline__ unsigned long long fmax2(unsigned long long a, unsigned long long b,
                                                    unsigned long long c) {
    unsigned long long r;
    asm("fma.rn.f32x2 %0, %1, %2, %3;" : "=l"(r) : "l"(a), "l"(b), "l"(c));
    return r;
}

__global__ __launch_bounds__(NTHREADS, 1)
void whd_fused(const float* __restrict__ pm,
               const float* __restrict__ gt,
               const float* __restrict__ osz,
               float* __restrict__ out)
{
    __shared__ unsigned long long s_gx[MM];     // (-gx,-gx) packed
    __shared__ unsigned long long s_gy[MM];     // (-gy,-gy) packed
    __shared__ unsigned s_wk[MM*(NWARP+1)];     // per-warp key-bit minima, stride 17
    __shared__ float    s_red[NWARP*2];
    __shared__ float    s_np[2*NBLOCKS];
    __shared__ bool     s_last;

    const int tid  = threadIdx.x;
    const int lane = tid & 31;
    const int wid  = tid >> 5;
    const int chunk = blockIdx.x;
    const int b     = blockIdx.y;

    const float fy = osz[2*b+0] * (1.0f/(float)HH);
    const float fx = osz[2*b+1] * (1.0f/(float)WW);

    if (tid < MM) {
        float gy = gt[((size_t)b*MM + tid)*2 + 0] * fy;
        float gx = gt[((size_t)b*MM + tid)*2 + 1] * fx;
        s_gx[tid] = pk2(-gx, -gx);
        s_gy[tid] = pk2(-gy, -gy);
    }

    // -------- stage per-pixel state into registers (packed pairs) --------
    unsigned long long nxp[PPK], nyp[PPK], csp[PPK];
    float pv[PPT], d2min[PPT];
    const float* pmb = pm + (size_t)b * NPIX;
    const int base = chunk * PIX_PER_BLOCK;
#pragma unroll
    for (int kk = 0; kk < PPK; ++kk) {
        int pixA = base + (2*kk  )*NTHREADS + tid;
        int pixB = base + (2*kk+1)*NTHREADS + tid;
        float pA = pmb[pixA];
        float pB = pmb[pixB];
        int yA = pixA / WW, xA = pixA - yA*WW;
        int yB = pixB / WW, xB = pixB - yB*WW;
        nxp[kk] = pk2((float)xA * fx, (float)xB * fx);
        nyp[kk] = pk2((float)yA * fy, (float)yB * fy);
        float ppA = pA*pA, ppB = pB*pB;
        float cA = 1.0f / (ppA*ppA + EPS_OVER_MAX);   // 1/(p^4 + eps/MAX)
        float cB = 1.0f / (ppB*ppB + EPS_OVER_MAX);
        csp[kk] = pk2(cA*cA, cB*cB);
        pv[2*kk] = pA; pv[2*kk+1] = pB;
        d2min[2*kk] = BIGF; d2min[2*kk+1] = BIGF;
    }
    __syncthreads();

    // -------- main pair loop: 192 GT points x 8 pixels/thread --------
#pragma unroll 2
    for (int j = 0; j < MM; ++j) {
        unsigned long long gx2 = s_gx[j];         // LDS.64 broadcast
        unsigned long long gy2 = s_gy[j];
        float kmin_a = BIGF, kmin_b = BIGF;       // two independent min chains
#pragma unroll
        for (int kk = 0; kk < PPK; ++kk) {
            unsigned long long dx = addx2(nxp[kk], gx2);
            unsigned long long dy = addx2(nyp[kk], gy2);
            unsigned long long d2 = fmax2(dx, dx, mulx2(dy, dy));
            float da, db; upk2(da, db, d2);
            d2min[2*kk]   = fminf(d2min[2*kk],   da);   // term1 per-pixel min over j
            d2min[2*kk+1] = fminf(d2min[2*kk+1], db);
            unsigned long long key = mulx2(d2, csp[kk]); // (d*c)^2 ordering key
            float ka, kb; upk2(ka, kb, key);
            kmin_a = fminf(kmin_a, ka);
            kmin_b = fminf(kmin_b, kb);
        }
        // single REDUX on key bits (nonneg floats -> uint order preserved)
        unsigned kb_ = __float_as_uint(fminf(kmin_a, kmin_b));
        unsigned rmin = __reduce_min_sync(0xffffffffu, kb_);
        if (lane == 0) s_wk[j*(NWARP+1)+wid] = rmin;
    }

    // -------- term1 partial: sum p * sqrt(min d2), and sum p --------
    float t1 = 0.f, ps = 0.f;
#pragma unroll
    for (int k = 0; k < PPT; ++k) { t1 += pv[k]*sqrtf(d2min[k]); ps += pv[k]; }
#pragma unroll
    for (int off = 16; off > 0; off >>= 1) {
        t1 += __shfl_down_sync(0xffffffffu, t1, off);
        ps += __shfl_down_sync(0xffffffffu, ps, off);
    }
    if (lane == 0) { s_red[wid] = t1; s_red[NWARP+wid] = ps; }
    __syncthreads();
    if (tid == 0) {
        float a = 0.f, c2 = 0.f;
#pragma unroll
        for (int w = 0; w < NWARP; ++w) { a += s_red[w]; c2 += s_red[NWARP+w]; }
        g_t1part[b*NCHUNK + chunk] = a;
        g_ppart [b*NCHUNK + chunk] = c2;
    }

    // -------- term2: combine per-warp minima; cross-block via atomicMax(~bits) --------
    if (tid < MM) {
        unsigned kmin = 0xFFFFFFFFu;
#pragma unroll
        for (int w = 0; w < NWARP; ++w)
            kmin = min(kmin, s_wk[tid*(NWARP+1)+w]);
        atomicMax(&g_jmin2[b*MM + tid], ~kmin);   // max(~bits) == min(key); 0 is identity
    }

    // -------- last-block finalize (saves a kernel launch) --------
    __threadfence();
    __syncthreads();
    if (tid == 0) s_last = (atomicAdd(&g_sem, 1u) == (unsigned)(NBLOCKS - 1));
    __syncthreads();
    if (!s_last) return;

    // stage term1 partials into smem in parallel
    if (tid < NBLOCKS) {
        s_np[tid]          = g_t1part[tid];
        s_np[NBLOCKS+tid]  = g_ppart[tid];
    }
    __syncthreads();

    // term2: 768 values; fixed-order deterministic sum
    float acc = 0.f;
#pragma unroll
    for (int t = tid; t < BB*MM; t += NTHREADS) {
        unsigned u = g_jmin2[t];
        float v = sqrtf(__uint_as_float(~u));      // sqrt(min key) = min d*c
        acc += fminf(v, MAX_DISTF);                // clip(., 0, MAX_DIST)
        g_jmin2[t] = 0u;                           // reset for next launch
    }
#pragma unroll
    for (int off = 16; off > 0; off >>= 1)
        acc += __shfl_down_sync(0xffffffffu, acc, off);
    if (lane == 0) s_red[wid] = acc;
    __syncthreads();

    if (tid == 0) {
        float t2 = 0.f;
#pragma unroll
        for (int w = 0; w < NWARP; ++w) t2 += s_red[w];
        float t1sum = 0.f;
#pragma unroll
        for (int bb = 0; bb < BB; ++bb) {
            float num = 0.f, den = 0.f;
#pragma unroll
            for (int c = 0; c < NCHUNK; ++c) {
                num += s_np[bb*NCHUNK + c];
                den += s_np[NBLOCKS + bb*NCHUNK + c];
            }
            t1sum += num / (den + EPSF);
        }
        out[0] = t1sum * (1.0f/(float)BB) + t2 * (1.0f/(float)(BB*MM));
        g_sem = 0u;                                // reset counter for next launch
    }
}

extern "C" void kernel_launch(void* const* d_in, const int* in_sizes, int n_in,
                              void* d_out, int out_size)
{
    const float* pm  = nullptr;
    const float* gt  = nullptr;
    const float* osz = nullptr;
    for (int i = 0; i < n_in; ++i) {
        if      (in_sizes[i] == BB*NPIX) pm  = (const float*)d_in[i];
        else if (in_sizes[i] == BB*MM*2) gt  = (const float*)d_in[i];
        else if (in_sizes[i] == BB*2)    osz = (const float*)d_in[i];
    }
    dim3 grid(NCHUNK, BB);
    whd_fused<<<grid, NTHREADS>>>(pm, gt, osz, (float*)d_out);
    (void)out_size;
}

// round 4
// speedup vs baseline: 2.2792x; 1.1669x over previous
#include <cuda_runtime.h>
#include <cstddef>

// ---- problem constants ----
#define HH 384
#define WW 384
#define NPIX (HH*WW)          // 147456
#define BB 4
#define MM 192
#define NT1 512
#define PPT 4
#define PPK (PPT/2)                    // 2 packed f32x2 pairs per thread
#define PIXBLK (NT1*PPT)               // 2048
#define NCHUNK (NPIX/PIXBLK)           // 72
#define NBLK1 (BB*NCHUNK)              // 288 -> 2 CTAs/SM, one wave on 148 SMs
#define NWARP1 (NT1/32)                // 16
#define EPSF 1e-6f
#define MAX_DISTF 543.0580079975699f   // sqrt(384^2+384^2)
#define EPS_OVER_MAX 1.8414263e-9f     // 1e-6 / MAX_DIST
#define C2MIN 0.999999f                // safe lower bound on c^2 (c >= 1/(1+eps'))
#define BIGF 3.4e38f

// term2 kernel config
#define NT2 256
#define W2 (NT2/32)                    // 8 warps/block, 1 warp per (b,j)
#define NBLK2 ((BB*MM)/W2)             // 96

// ---- scratch (static device globals; g_sem reset by finalizer each launch) ----
__device__ float    g_t1part[NBLK1];
__device__ float    g_ppart [NBLK1];
__device__ float    g_jval  [BB*MM];
__device__ unsigned g_sem;

// ---- packed f32x2 helpers ----
__device__ __forceinline__ unsigned long long pk2(float a, float b) {
    unsigned long long r;
    asm("mov.b64 %0, {%1, %2};" : "=l"(r) : "f"(a), "f"(b));
    return r;
}
__device__ __forceinline__ void upk2(float& a, float& b, unsigned long long v) {
    asm("mov.b64 {%0, %1}, %2;" : "=f"(a), "=f"(b) : "l"(v));
}
__device__ __forceinline__ unsigned long long addx2(unsigned long long a, unsigned long long b) {
    unsigned long long r;
    asm("add.rn.f32x2 %0, %1, %2;" : "=l"(r) : "l"(a), "l"(b));
    return r;
}
__device__ __forceinline__ unsigned long long mulx2(unsigned long long a, unsigned long long b) {
    unsigned long long r;
    asm("mul.rn.f32x2 %0, %1, %2;" : "=l"(r) : "l"(a), "l"(b));
    return r;
}
__device__ __forceinline__ unsigned long long fmax2(unsigned long long a, unsigned long long b,
                                                    unsigned long long c) {
    unsigned long long r;
    asm("fma.rn.f32x2 %0, %1, %2, %3;" : "=l"(r) : "l"(a), "l"(b), "l"(c));
    return r;
}

// ============================================================================
// Kernel A: term2 via exact windowed search. One warp per (b,j).
// min over ALL pixels of d2*c^2 where c = 1/(p^4 + eps/MAX). Since c^2 >= C2MIN,
// a window with edge-gap G (normalized) certifies exactness when U <= G^2*C2MIN.
// Expand geometrically until certified (full image => all sides clipped => pass).
// ============================================================================
__global__ __launch_bounds__(NT2)
void whd_term2(const float* __restrict__ pm,
               const float* __restrict__ gt,
               const float* __restrict__ osz)
{
    const int lane = threadIdx.x & 31;
    const int wid  = threadIdx.x >> 5;
    const int wg   = blockIdx.x * W2 + wid;          // 0..767
    const int b    = wg / MM;
    const int j    = wg - b * MM;

    const float fy = osz[2*b+0] * (1.0f/(float)HH);
    const float fx = osz[2*b+1] * (1.0f/(float)WW);
    const float grow = gt[((size_t)b*MM + j)*2 + 0]; // row (y), resized coords
    const float gcol = gt[((size_t)b*MM + j)*2 + 1]; // col (x)
    const float* pmb = pm + (size_t)b * NPIX;

    const int cx = (int)gcol;                        // gt in [0,384)
    const int cy = (int)grow;

    float U;
    int r = 8;
    for (;;) {
        int x0 = cx - r, x1 = cx + r, y0 = cy - r, y1 = cy + r;
        const bool clx0 = (x0 <= 0), clx1 = (x1 >= WW-1);
        const bool cly0 = (y0 <= 0), cly1 = (y1 >= HH-1);
        x0 = max(x0, 0); y0 = max(y0, 0);
        x1 = min(x1, WW-1); y1 = min(y1, HH-1);
        const int wnd = x1 - x0 + 1;
        const int cnt = wnd * (y1 - y0 + 1);

        float kmin = BIGF;
        for (int idx = lane; idx < cnt; idx += 32) {
            int q  = idx / wnd;
            int px = x0 + (idx - q*wnd);
            int py = y0 + q;
            float p  = pmb[py*WW + px];
            float dx = ((float)px - gcol) * fx;
            float dy = ((float)py - grow) * fy;
            float d2 = fmaf(dx, dx, dy*dy);
            float pp = p*p;
            float c  = 1.0f / (pp*pp + EPS_OVER_MAX);
            kmin = fminf(kmin, d2 * (c*c));
        }
        unsigned u = __reduce_min_sync(0xffffffffu, __float_as_uint(kmin));
        U = __uint_as_float(u);

        // min normalized distance from GT to any real pixel OUTSIDE the window
        float gxl = clx0 ? BIGF : (gcol - (float)x0 + 1.0f) * fx;
        float gxh = clx1 ? BIGF : ((float)x1 + 1.0f - gcol) * fx;
        float gyl = cly0 ? BIGF : (grow - (float)y0 + 1.0f) * fy;
        float gyh = cly1 ? BIGF : ((float)y1 + 1.0f - grow) * fy;
        float G = fminf(fminf(gxl, gxh), fminf(gyl, gyh));
        if (U <= G*G*C2MIN) break;                   // exactness certified
        r <<= 1;                                     // expand (terminates: full image)
    }
    if (lane == 0)
        g_jval[wg] = fminf(sqrtf(U), MAX_DISTF);     // clip(., 0, MAX_DIST)
}

// ============================================================================
// Kernel B: term1 over all N x M pairs (pure: no term2 bookkeeping) + fused
// last-block finalize combining g_t1part/g_ppart (own blocks) and g_jval
// (written by whd_term2, launched earlier on the same stream).
// ============================================================================
__global__ __launch_bounds__(NT1, 2)
void whd_term1(const float* __restrict__ pm,
               const float* __restrict__ gt,
               const float* __restrict__ osz,
               float* __restrict__ out)
{
    __shared__ ulonglong2 s_g[MM];        // {(-gx,-gx), (-gy,-gy)} packed -> LDS.128
    __shared__ float s_red[NWARP1*2];
    __shared__ float s_t1[BB];
    __shared__ bool  s_last;

    const int tid  = threadIdx.x;
    const int lane = tid & 31;
    const int wid  = tid >> 5;
    const int chunk = blockIdx.x;
    const int b     = blockIdx.y;

    const float fy = osz[2*b+0] * (1.0f/(float)HH);
    const float fx = osz[2*b+1] * (1.0f/(float)WW);

    if (tid < MM) {
        float gy = gt[((size_t)b*MM + tid)*2 + 0] * fy;
        float gx = gt[((size_t)b*MM + tid)*2 + 1] * fx;
        ulonglong2 v;
        v.x = pk2(-gx, -gx);
        v.y = pk2(-gy, -gy);
        s_g[tid] = v;
    }

    // -------- stage per-pixel state (packed pairs) --------
    unsigned long long nxp[PPK], nyp[PPK];
    float pv[PPT], d2min[PPT];
    const float* pmb = pm + (size_t)b * NPIX;
    const int base = chunk * PIXBLK;
#pragma unroll
    for (int kk = 0; kk < PPK; ++kk) {
        int pixA = base + (2*kk  )*NT1 + tid;         // coalesced
        int pixB = base + (2*kk+1)*NT1 + tid;
        float pA = pmb[pixA];
        float pB = pmb[pixB];
        int yA = pixA / WW, xA = pixA - yA*WW;
        int yB = pixB / WW, xB = pixB - yB*WW;
        nxp[kk] = pk2((float)xA * fx, (float)xB * fx);
        nyp[kk] = pk2((float)yA * fy, (float)yB * fy);
        pv[2*kk] = pA; pv[2*kk+1] = pB;
        d2min[2*kk] = BIGF; d2min[2*kk+1] = BIGF;
    }
    __syncthreads();

    // -------- hot loop: 192 GT points x 4 pixels/thread, term1 only --------
#pragma unroll 4
    for (int j = 0; j < MM; ++j) {
        ulonglong2 g = s_g[j];                        // single LDS.128 broadcast
#pragma unroll
        for (int kk = 0; kk < PPK; ++kk) {
            unsigned long long dx = addx2(nxp[kk], g.x);
            unsigned long long dy = addx2(nyp[kk], g.y);
            unsigned long long d2 = fmax2(dx, dx, mulx2(dy, dy));
            float da, db; upk2(da, db, d2);
            d2min[2*kk]   = fminf(d2min[2*kk],   da);
            d2min[2*kk+1] = fminf(d2min[2*kk+1], db);
        }
    }

    // -------- term1 partial: sum p*sqrt(min d2), sum p --------
    float t1 = 0.f, ps = 0.f;
#pragma unroll
    for (int k = 0; k < PPT; ++k) { t1 += pv[k]*sqrtf(d2min[k]); ps += pv[k]; }
#pragma unroll
    for (int off = 16; off > 0; off >>= 1) {
        t1 += __shfl_down_sync(0xffffffffu, t1, off);
        ps += __shfl_down_sync(0xffffffffu, ps, off);
    }
    if (lane == 0) { s_red[wid] = t1; s_red[NWARP1+wid] = ps; }
    __syncthreads();
    if (tid == 0) {
        float a = 0.f, c2 = 0.f;
#pragma unroll
        for (int w = 0; w < NWARP1; ++w) { a += s_red[w]; c2 += s_red[NWARP1+w]; }
        g_t1part[b*NCHUNK + chunk] = a;
        g_ppart [b*NCHUNK + chunk] = c2;
    }

    // -------- last-block finalize --------
    __threadfence();
    __syncthreads();
    if (tid == 0) s_last = (atomicAdd(&g_sem, 1u) == (unsigned)(NBLK1 - 1));
    __syncthreads();
    if (!s_last) return;

    // term2 total: fixed-order deterministic sum of 768 precomputed values
    float acc = 0.f;
#pragma unroll
    for (int t = tid; t < BB*MM; t += NT1) acc += g_jval[t];
#pragma unroll
    for (int off = 16; off > 0; off >>= 1)
        acc += __shfl_down_sync(0xffffffffu, acc, off);

    // term1 ratios: warps 0..3 handle one image each (fixed-order shfl reduce)
    if (wid < BB) {
        float nu = 0.f, de = 0.f;
        for (int c = lane; c < NCHUNK; c += 32) {
            nu += g_t1part[wid*NCHUNK + c];
            de += g_ppart [wid*NCHUNK + c];
        }
#pragma unroll
        for (int off = 16; off > 0; off >>= 1) {
            nu += __shfl_down_sync(0xffffffffu, nu, off);
            de += __shfl_down_sync(0xffffffffu, de, off);
        }
        if (lane == 0) s_t1[wid] = nu / (de + EPSF);
    }
    if (lane == 0) s_red[wid] = acc;   // safe: all warps past earlier s_red reads
    __syncthreads();

    if (tid == 0) {
        float t2 = 0.f;
#pragma unroll
        for (int w = 0; w < NWARP1; ++w) t2 += s_red[w];
        float t1sum = 0.f;
#pragma unroll
        for (int bb = 0; bb < BB; ++bb) t1sum += s_t1[bb];
        out[0] = t1sum * (1.0f/(float)BB) + t2 * (1.0f/(float)(BB*MM));
        g_sem = 0u;                                   // reset for next replay
    }
}

extern "C" void kernel_launch(void* const* d_in, const int* in_sizes, int n_in,
                              void* d_out, int out_size)
{
    const float* pm  = nullptr;
    const float* gt  = nullptr;
    const float* osz = nullptr;
    for (int i = 0; i < n_in; ++i) {
        if      (in_sizes[i] == BB*NPIX) pm  = (const float*)d_in[i];
        else if (in_sizes[i] == BB*MM*2) gt  = (const float*)d_in[i];
        else if (in_sizes[i] == BB*2)    osz = (const float*)d_in[i];
    }
    // term2 first (independent of term1); term1's last block finalizes both.
    whd_term2<<<NBLK2, NT2>>>(pm, gt, osz);
    dim3 grid(NCHUNK, BB);
    whd_term1<<<grid, NT1>>>(pm, gt, osz, (float*)d_out);
    (void)out_size;
}

// round 6
// speedup vs baseline: 4.5942x; 2.0157x over previous
#include <cuda_runtime.h>
#include <cstddef>

// ---- problem constants ----
#define HH 384
#define WW 384
#define NPIX (HH*WW)          // 147456
#define BB 4
#define MM 192
#define NT 512
#define TILE_W 64
#define TILE_H 32
#define TILES_X (WW/TILE_W)            // 6
#define TILES_Y (HH/TILE_H)            // 12
#define NCHUNK (TILES_X*TILES_Y)       // 72
#define NBLK1 (BB*NCHUNK)              // 288
#define NBLK2 ((BB*MM)/16)             // 48 (16 warps/block, 1 warp per (b,j))
#define TOTBLK (NBLK1+NBLK2)           // 336
#define NWARP (NT/32)                  // 16
#define EPSF 1e-6f
#define MAX_DISTF 543.0580079975699f   // sqrt(384^2+384^2)
#define EPS_OVER_MAX 1.8414263e-9f     // 1e-6 / MAX_DIST
#define C2MIN 0.999999f
#define BIGF 3.4e38f

// ---- scratch (static device globals; g_sem reset by finalizer) ----
__device__ float    g_t1part[NBLK1];
__device__ float    g_ppart [NBLK1];
__device__ float    g_jval  [BB*MM];
__device__ unsigned g_sem;

// ---- packed f32x2 helpers ----
__device__ __forceinline__ unsigned long long pk2(float a, float b) {
    unsigned long long r;
    asm("mov.b64 %0, {%1, %2};" : "=l"(r) : "f"(a), "f"(b));
    return r;
}
__device__ __forceinline__ void upk2(float& a, float& b, unsigned long long v) {
    asm("mov.b64 {%0, %1}, %2;" : "=f"(a), "=f"(b) : "l"(v));
}
__device__ __forceinline__ unsigned long long addx2(unsigned long long a, unsigned long long b) {
    unsigned long long r;
    asm("add.rn.f32x2 %0, %1, %2;" : "=l"(r) : "l"(a), "l"(b));
    return r;
}
__device__ __forceinline__ unsigned long long fmax2(unsigned long long a, unsigned long long b,
                                                    unsigned long long c) {
    unsigned long long r;
    asm("fma.rn.f32x2 %0, %1, %2, %3;" : "=l"(r) : "l"(a), "l"(b), "l"(c));
    return r;
}

__global__ __launch_bounds__(NT, 2)
void whd_all(const float* __restrict__ pm,
             const float* __restrict__ gt,
             const float* __restrict__ osz,
             float* __restrict__ out)
{
    __shared__ float              s_gxs[MM];   // -gx of candidates
    __shared__ unsigned long long s_gy2[MM];   // (-gy,-gy) packed
    __shared__ float s_red[NWARP*2];
    __shared__ float s_t1[BB];
    __shared__ int   s_n;
    __shared__ bool  s_last;

    const int tid  = threadIdx.x;
    const int lane = tid & 31;
    const int wid  = tid >> 5;
    const int bid  = blockIdx.x;

    if (tid == 0) s_n = 0;

    if (bid < NBLK2) {
        // ==================== term2 role: one warp per (b,j) ====================
        // Exact windowed search for min over all pixels of d2*c^2 (c^2 >= C2MIN
        // => certifiable by edge-gap bound). Expands until certified; when all
        // sides clip, every side-gap is "infinite" and we accept unconditionally.
        const int wg = bid * NWARP + wid;          // 0..767
        const int b  = wg / MM;
        const int j  = wg - b * MM;

        const float fy = osz[2*b+0] * (1.0f/(float)HH);
        const float fx = osz[2*b+1] * (1.0f/(float)WW);
        const float grow = gt[((size_t)b*MM + j)*2 + 0];
        const float gcol = gt[((size_t)b*MM + j)*2 + 1];
        const float* pmb = pm + (size_t)b * NPIX;

        const int cx = (int)gcol;
        const int cy = (int)grow;

        float U;
        int r = 8;
        for (;;) {
            int x0 = cx - r, x1 = cx + r, y0 = cy - r, y1 = cy + r;
            const bool clx0 = (x0 <= 0), clx1 = (x1 >= WW-1);
            const bool cly0 = (y0 <= 0), cly1 = (y1 >= HH-1);
            x0 = max(x0, 0); y0 = max(y0, 0);
            x1 = min(x1, WW-1); y1 = min(y1, HH-1);
            const int wnd = x1 - x0 + 1;
            const int cnt = wnd * (y1 - y0 + 1);

            float kmin = BIGF;
            for (int idx = lane; idx < cnt; idx += 32) {
                int q  = idx / wnd;
                int px = x0 + (idx - q*wnd);
                int py = y0 + q;
                float p  = pmb[py*WW + px];
                float dx = ((float)px - gcol) * fx;
                float dy = ((float)py - grow) * fy;
                float d2 = fmaf(dx, dx, dy*dy);
                float pp = p*p;
                float c  = 1.0f / (pp*pp + EPS_OVER_MAX);
                kmin = fminf(kmin, d2 * (c*c));
            }
            unsigned u = __reduce_min_sync(0xffffffffu, __float_as_uint(kmin));
            U = __uint_as_float(u);

            if (clx0 && clx1 && cly0 && cly1) break;   // full image: exact by construction

            const float GBIG = 1.0e18f;                // finite "no gap on this side"
            float gxl = clx0 ? GBIG : (gcol - (float)x0 + 1.0f) * fx;
            float gxh = clx1 ? GBIG : ((float)x1 + 1.0f - gcol) * fx;
            float gyl = cly0 ? GBIG : (grow - (float)y0 + 1.0f) * fy;
            float gyh = cly1 ? GBIG : ((float)y1 + 1.0f - grow) * fy;
            float G = fminf(fminf(gxl, gxh), fminf(gyl, gyh));
            if (U <= G*G*C2MIN) break;                 // exactness certified
            r <<= 1;
        }
        if (lane == 0)
            g_jval[wg] = fminf(sqrtf(U), MAX_DISTF);
    } else {
        // ==================== term1 role: one 64x32 pixel tile ====================
        const int tb    = bid - NBLK2;             // 0..287
        const int b     = tb / NCHUNK;
        const int chunk = tb - b * NCHUNK;
        const int tile_x = chunk % TILES_X;
        const int tile_y = chunk / TILES_X;

        const float fy = osz[2*b+0] * (1.0f/(float)HH);
        const float fx = osz[2*b+1] * (1.0f/(float)WW);
        const float* pmb = pm + (size_t)b * NPIX;

        const int col0 = tile_x * TILE_W;
        const int row0 = tile_y * TILE_H;
        const int colg = col0 + (tid & 63);
        const int rowb = row0 + (tid >> 6);        // rows rowb, rowb+8, +16, +24

        // issue pixel loads early (overlap with phase-0 cull)
        float p0 = pmb[(rowb +  0)*WW + colg];
        float p1 = pmb[(rowb +  8)*WW + colg];
        float p2 = pmb[(rowb + 16)*WW + colg];
        float p3 = pmb[(rowb + 24)*WW + colg];

        const float xn  = (float)colg * fx;        // shared across this thread's 4 px
        const float yn0 = (float)(rowb +  0) * fy;
        const float yn1 = (float)(rowb +  8) * fy;
        const float yn2 = (float)(rowb + 16) * fy;
        const float yn3 = (float)(rowb + 24) * fy;
        const unsigned long long ny01 = pk2(yn0, yn1);
        const unsigned long long ny23 = pk2(yn2, yn3);

        // ---- phase 0: exact candidate culling (triangle inequality) ----
        const float cxn = ((float)col0 + 31.5f) * fx;
        const float cyn = ((float)row0 + 15.5f) * fy;
        const float hx = 31.5f * fx, hy = 15.5f * fy;
        const float Dh = sqrtf(hx*hx + hy*hy);     // tile half-diagonal (normalized)

        float dc = BIGF, gxn = 0.f, gyn = 0.f;
        if (tid < MM) {
            gyn = gt[((size_t)b*MM + tid)*2 + 0] * fy;
            gxn = gt[((size_t)b*MM + tid)*2 + 1] * fx;
            float ax = gxn - cxn, ay = gyn - cyn;
            dc = sqrtf(fmaf(ax, ax, ay*ay));
        }
        unsigned wm = __reduce_min_sync(0xffffffffu, __float_as_uint(dc));
        if (lane == 0) s_red[wid] = __uint_as_float(wm);
        __syncthreads();
        float Uc = fminf(fminf(fminf(s_red[0], s_red[1]), fminf(s_red[2], s_red[3])),
                         fminf(s_red[4], s_red[5]));
        // point j can be some tile pixel's argmin only if dc <= Uc + 2*Dh (+ slack)
        float thr = Uc + 2.0f*Dh + 1e-2f;
        if (tid < MM && dc <= thr) {
            int slot = atomicAdd(&s_n, 1);
            s_gxs[slot] = -gxn;
            s_gy2[slot] = pk2(-gyn, -gyn);
        }
        __syncthreads();
        const int ncand = s_n;

        // ---- hot loop over candidates only ----
        float d0 = BIGF, d1 = BIGF, d2m = BIGF, d3 = BIGF;
#pragma unroll 2
        for (int jj = 0; jj < ncand; ++jj) {
            float gxs = s_gxs[jj];                 // LDS broadcast
            unsigned long long gy2 = s_gy2[jj];
            float dx  = xn + gxs;
            float dxx = dx * dx;
            unsigned long long dxx2 = pk2(dxx, dxx);
            unsigned long long dya = addx2(ny01, gy2);
            unsigned long long d2a = fmax2(dya, dya, dxx2);
            unsigned long long dyb = addx2(ny23, gy2);
            unsigned long long d2b = fmax2(dyb, dyb, dxx2);
            float a, bx, c, dd;
            upk2(a, bx, d2a); upk2(c, dd, d2b);
            d0  = fminf(d0,  a);
            d1  = fminf(d1,  bx);
            d2m = fminf(d2m, c);
            d3  = fminf(d3,  dd);
        }

        // ---- term1 partial: sum p*sqrt(min d2), sum p ----
        float t1 = p0*sqrtf(d0) + p1*sqrtf(d1) + p2*sqrtf(d2m) + p3*sqrtf(d3);
        float ps = p0 + p1 + p2 + p3;
#pragma unroll
        for (int off = 16; off > 0; off >>= 1) {
            t1 += __shfl_down_sync(0xffffffffu, t1, off);
            ps += __shfl_down_sync(0xffffffffu, ps, off);
        }
        __syncthreads();   // protect s_red reuse
        if (lane == 0) { s_red[wid] = t1; s_red[NWARP+wid] = ps; }
        __syncthreads();
        if (tid == 0) {
            float a = 0.f, c2 = 0.f;
#pragma unroll
            for (int w = 0; w < NWARP; ++w) { a += s_red[w]; c2 += s_red[NWARP+w]; }
            g_t1part[tb] = a;
            g_ppart [tb] = c2;
        }
    }

    // ==================== common tail: last-block finalize ====================
    __threadfence();
    __syncthreads();
    if (tid == 0) s_last = (atomicAdd(&g_sem, 1u) == (unsigned)(TOTBLK - 1));
    __syncthreads();
    if (!s_last) return;

    // term2 total: fixed-order deterministic sum of 768 values
    float acc = 0.f;
#pragma unroll
    for (int t = tid; t < BB*MM; t += NT) acc += g_jval[t];
#pragma unroll
    for (int off = 16; off > 0; off >>= 1)
        acc += __shfl_down_sync(0xffffffffu, acc, off);

    // term1 ratios: warps 0..3, one image each (fixed-order)
    if (wid < BB) {
        float nu = 0.f, de = 0.f;
        for (int c = lane; c < NCHUNK; c += 32) {
            nu += g_t1part[wid*NCHUNK + c];
            de += g_ppart [wid*NCHUNK + c];
        }
#pragma unroll
        for (int off = 16; off > 0; off >>= 1) {
            nu += __shfl_down_sync(0xffffffffu, nu, off);
            de += __shfl_down_sync(0xffffffffu, de, off);
        }
        if (lane == 0) s_t1[wid] = nu / (de + EPSF);
    }
    if (lane == 0) s_red[wid] = acc;
    __syncthreads();

    if (tid == 0) {
        float t2 = 0.f;
#pragma unroll
        for (int w = 0; w < NWARP; ++w) t2 += s_red[w];
        float t1sum = 0.f;
#pragma unroll
        for (int bb = 0; bb < BB; ++bb) t1sum += s_t1[bb];
        out[0] = t1sum * (1.0f/(float)BB) + t2 * (1.0f/(float)(BB*MM));
        g_sem = 0u;                                // reset for next replay
    }
}

extern "C" void kernel_launch(void* const* d_in, const int* in_sizes, int n_in,
                              void* d_out, int out_size)
{
    const float* pm  = nullptr;
    const float* gt  = nullptr;
    const float* osz = nullptr;
    for (int i = 0; i < n_in; ++i) {
        if      (in_sizes[i] == BB*NPIX) pm  = (const float*)d_in[i];
        else if (in_sizes[i] == BB*MM*2) gt  = (const float*)d_in[i];
        else if (in_sizes[i] == BB*2)    osz = (const float*)d_in[i];
    }
    whd_all<<<TOTBLK, NT>>>(pm, gt, osz, (float*)d_out);
    (void)out_size;
}